// round 9
// baseline (speedup 1.0000x reference)
#include <cuda_runtime.h>
#include <cuda_fp16.h>
#include <math.h>

#define NMAX 100000
#define EMAX 1600000
#define HH 4
#define DD 32
#define HDIM 128
#define INF_ 128
#define NEG_SLOPE 0.2f

typedef unsigned long long ull;
typedef unsigned int uint_;

// Scratch (device globals — no allocation)
__device__ __align__(16) __half g_hh[NMAX * HDIM];   // [n][h][d] fp16
__device__ __align__(16) float g_el[NMAX * HH];
__device__ __align__(16) float g_er[NMAX * HH];
__device__ int g_deg[NMAX];
__device__ int g_off[NMAX];
__device__ int g_cursor[NMAX];
__device__ int g_bsum[128];
__device__ int g_csr_src[EMAX];

// Side stream + events (static-init, before harness mem checkpoints)
struct AuxStreams {
    cudaStream_t s2;
    cudaEvent_t evF, evJ;
    AuxStreams() {
        cudaStreamCreateWithFlags(&s2, cudaStreamNonBlocking);
        cudaEventCreateWithFlags(&evF, cudaEventDisableTiming);
        cudaEventCreateWithFlags(&evJ, cudaEventDisableTiming);
    }
};
static AuxStreams g_aux;

__device__ __forceinline__ float lrelu(float x) {
    return x > 0.f ? x : NEG_SLOPE * x;
}
__device__ __forceinline__ ull pk2(float lo, float hi) {
    ull r;
    asm("mov.b64 %0, {%1, %2};" : "=l"(r) : "f"(lo), "f"(hi));
    return r;
}
__device__ __forceinline__ void upk2(ull v, float& lo, float& hi) {
    asm("mov.b64 {%0, %1}, %2;" : "=f"(lo), "=f"(hi) : "l"(v));
}
__device__ __forceinline__ void ffma2(ull& d, ull a, ull b) {
    asm("fma.rn.f32x2 %0, %1, %2, %0;" : "+l"(d) : "l"(a), "l"(b));
}
__device__ __forceinline__ void cpa16(uint_ s, const void* g) {
    asm volatile("cp.async.cg.shared.global [%0], [%1], 16;" :: "r"(s), "l"(g));
}
__device__ __forceinline__ void cpa_commit() {
    asm volatile("cp.async.commit_group;");
}
__device__ __forceinline__ void cpa_wait_all() {
    asm volatile("cp.async.wait_group 0;");
}

// ---------------------------------------------------------------------------
__global__ void init_kernel(int N) {
    int i = blockIdx.x * blockDim.x + threadIdx.x;
    if (i < N) g_deg[i] = 0;
    if (i < 128) g_bsum[i] = -1;
}

// ---------------------------------------------------------------------------
// GEMM + fused el/er, double-buffered cp.async.  (frozen since R7)
// ---------------------------------------------------------------------------
__global__ void __launch_bounds__(256, 2)
gemm_elr_kernel(const float* __restrict__ feat,
                const float* __restrict__ W,
                const float* __restrict__ attn_l,
                const float* __restrict__ attn_r, int N) {
    __shared__ float sW[2][32][128];
    __shared__ float sFT[2][32][132];

    const int tid = threadIdx.x;
    const int row0 = blockIdx.x * 128;
    const int ry = tid >> 4;
    const int cx = tid & 15;
    const int r0 = ry * 8;
    const int c0a = 4 * cx;
    const int c0b = 64 + 4 * cx;
    const int hA = (cx < 8) ? 0 : 1;
    const int d0 = c0a & 31;

    int wk[4], wc4[4];
#pragma unroll
    for (int i = 0; i < 4; i++) {
        int idx = tid + i * 256;
        wk[i] = idx >> 5;
        wc4[i] = idx & 31;
    }
    int fr[4], fq[4];
#pragma unroll
    for (int i = 0; i < 4; i++) {
        int idx = tid + i * 256;
        fr[i] = idx >> 3;
        fq[i] = idx & 7;
    }

    ull acc2[32];
#pragma unroll
    for (int i = 0; i < 32; i++) acc2[i] = 0ull;

#pragma unroll
    for (int i = 0; i < 4; i++)
        cpa16((uint_)__cvta_generic_to_shared(&sW[0][wk[i]][wc4[i] * 4]),
              &W[wk[i] * HDIM + wc4[i] * 4]);
    cpa_commit();
    float4 fstage[4];
#pragma unroll
    for (int i = 0; i < 4; i++) {
        fstage[i] = make_float4(0.f, 0.f, 0.f, 0.f);
        if (row0 + fr[i] < N)
            fstage[i] = *reinterpret_cast<const float4*>(
                &feat[(size_t)(row0 + fr[i]) * INF_ + 4 * fq[i]]);
    }

    for (int kc = 0; kc < 4; kc++) {
        const int cur = kc & 1;
#pragma unroll
        for (int i = 0; i < 4; i++) {
            sFT[cur][4 * fq[i] + 0][fr[i]] = fstage[i].x;
            sFT[cur][4 * fq[i] + 1][fr[i]] = fstage[i].y;
            sFT[cur][4 * fq[i] + 2][fr[i]] = fstage[i].z;
            sFT[cur][4 * fq[i] + 3][fr[i]] = fstage[i].w;
        }
        cpa_wait_all();
        __syncthreads();

        if (kc < 3) {
            const int nxt = cur ^ 1;
            const int k0n = (kc + 1) * 32;
#pragma unroll
            for (int i = 0; i < 4; i++)
                cpa16((uint_)__cvta_generic_to_shared(&sW[nxt][wk[i]][wc4[i] * 4]),
                      &W[(k0n + wk[i]) * HDIM + wc4[i] * 4]);
            cpa_commit();
#pragma unroll
            for (int i = 0; i < 4; i++) {
                fstage[i] = make_float4(0.f, 0.f, 0.f, 0.f);
                if (row0 + fr[i] < N)
                    fstage[i] = *reinterpret_cast<const float4*>(
                        &feat[(size_t)(row0 + fr[i]) * INF_ + k0n + 4 * fq[i]]);
            }
        }

#pragma unroll 8
        for (int k = 0; k < 32; k++) {
            ulonglong2 f01 = *reinterpret_cast<const ulonglong2*>(&sFT[cur][k][r0]);
            ulonglong2 f23 = *reinterpret_cast<const ulonglong2*>(&sFT[cur][k][r0 + 4]);
            float4 wa = *reinterpret_cast<const float4*>(&sW[cur][k][c0a]);
            float4 wb = *reinterpret_cast<const float4*>(&sW[cur][k][c0b]);
            ull fp[4] = { f01.x, f01.y, f23.x, f23.y };
            ull wd[8] = { pk2(wa.x, wa.x), pk2(wa.y, wa.y),
                          pk2(wa.z, wa.z), pk2(wa.w, wa.w),
                          pk2(wb.x, wb.x), pk2(wb.y, wb.y),
                          pk2(wb.z, wb.z), pk2(wb.w, wb.w) };
#pragma unroll
            for (int rp = 0; rp < 4; rp++)
#pragma unroll
                for (int c = 0; c < 8; c++)
                    ffma2(acc2[rp * 8 + c], fp[rp], wd[c]);
        }
        __syncthreads();
    }

    float al[8], ar[8];
#pragma unroll
    for (int c = 0; c < 4; c++) {
        al[c]     = __ldg(&attn_l[c0a + c]);
        al[4 + c] = __ldg(&attn_l[c0b + c]);
        ar[c]     = __ldg(&attn_r[c0a + c]);
        ar[4 + c] = __ldg(&attn_r[c0b + c]);
    }

#pragma unroll
    for (int i = 0; i < 8; i++) {
        int rp = i >> 1, hi = i & 1;
        float hv[8];
#pragma unroll
        for (int c = 0; c < 8; c++) {
            float lo, hh;
            upk2(acc2[rp * 8 + c], lo, hh);
            hv[c] = hi ? hh : lo;
        }
        int row = row0 + r0 + i;
        bool valid = row < N;
        if (valid) {
            __half2 p0 = __floats2half2_rn(hv[0], hv[1]);
            __half2 p1 = __floats2half2_rn(hv[2], hv[3]);
            __half2 p2 = __floats2half2_rn(hv[4], hv[5]);
            __half2 p3 = __floats2half2_rn(hv[6], hv[7]);
            uint2 va = make_uint2(*(unsigned*)&p0, *(unsigned*)&p1);
            uint2 vb = make_uint2(*(unsigned*)&p2, *(unsigned*)&p3);
            *reinterpret_cast<uint2*>(&g_hh[((size_t)row * HH + hA) * DD + d0]) = va;
            *reinterpret_cast<uint2*>(&g_hh[((size_t)row * HH + hA + 2) * DD + d0]) = vb;
        }
        float plA = hv[0] * al[0] + hv[1] * al[1] + hv[2] * al[2] + hv[3] * al[3];
        float plB = hv[4] * al[4] + hv[5] * al[5] + hv[6] * al[6] + hv[7] * al[7];
        float prA = hv[0] * ar[0] + hv[1] * ar[1] + hv[2] * ar[2] + hv[3] * ar[3];
        float prB = hv[4] * ar[4] + hv[5] * ar[5] + hv[6] * ar[6] + hv[7] * ar[7];
#pragma unroll
        for (int o = 1; o <= 4; o <<= 1) {
            plA += __shfl_xor_sync(0xffffffffu, plA, o);
            plB += __shfl_xor_sync(0xffffffffu, plB, o);
            prA += __shfl_xor_sync(0xffffffffu, prA, o);
            prB += __shfl_xor_sync(0xffffffffu, prB, o);
        }
        if (valid) {
            if (cx == 0) {
                g_el[row * HH + 0] = plA; g_el[row * HH + 2] = plB;
                g_er[row * HH + 0] = prA; g_er[row * HH + 2] = prB;
            } else if (cx == 8) {
                g_el[row * HH + 1] = plA; g_el[row * HH + 3] = plB;
                g_er[row * HH + 1] = prA; g_er[row * HH + 3] = prB;
            }
        }
    }
}

// ---------------------------------------------------------------------------
// CSR build (int4-vectorized index reads)
// ---------------------------------------------------------------------------
__global__ void hist_kernel(const int* __restrict__ dst, int E) {
    int i = blockIdx.x * blockDim.x + threadIdx.x;
    int base = i * 4;
    if (base + 3 < E) {
        int4 d = *reinterpret_cast<const int4*>(&dst[base]);
        atomicAdd(&g_deg[d.x], 1);
        atomicAdd(&g_deg[d.y], 1);
        atomicAdd(&g_deg[d.z], 1);
        atomicAdd(&g_deg[d.w], 1);
    } else {
        for (int j = base; j < E; j++) atomicAdd(&g_deg[dst[j]], 1);
    }
}

// Single-kernel scan with decoupled lookback (<=128 co-resident blocks).
__global__ void scan_fused_kernel(int N) {
    __shared__ int sm[1024];
    __shared__ int spre[128];
    int tid = threadIdx.x;
    int b = blockIdx.x;
    int gid = b * 1024 + tid;
    int v = (gid < N) ? g_deg[gid] : 0;
    sm[tid] = v;
    __syncthreads();
#pragma unroll
    for (int o = 1; o < 1024; o <<= 1) {
        int t = (tid >= o) ? sm[tid - o] : 0;
        __syncthreads();
        sm[tid] += t;
        __syncthreads();
    }
    if (tid == 0) atomicExch(&g_bsum[b], sm[1023]);
    int pv = 0;
    if (tid < b) {
        volatile int* p = &g_bsum[tid];
        int x;
        do { x = *p; } while (x < 0);
        pv = x;
    }
    if (tid < 128) spre[tid] = pv;
    __syncthreads();
#pragma unroll
    for (int o = 64; o > 0; o >>= 1) {
        if (tid < o) spre[tid] += spre[tid + o];
        __syncthreads();
    }
    int prefix = spre[0];
    if (gid < N) {
        int o = sm[tid] - v + prefix;
        g_off[gid] = o;
        g_cursor[gid] = o;
    }
}

__global__ void scatter_kernel(const int* __restrict__ src,
                               const int* __restrict__ dst, int E) {
    int i = blockIdx.x * blockDim.x + threadIdx.x;
    int base = i * 4;
    if (base + 3 < E) {
        int4 d = *reinterpret_cast<const int4*>(&dst[base]);
        int4 s = *reinterpret_cast<const int4*>(&src[base]);
        int p0 = atomicAdd(&g_cursor[d.x], 1);
        int p1 = atomicAdd(&g_cursor[d.y], 1);
        int p2 = atomicAdd(&g_cursor[d.z], 1);
        int p3 = atomicAdd(&g_cursor[d.w], 1);
        g_csr_src[p0] = s.x;
        g_csr_src[p1] = s.y;
        g_csr_src[p2] = s.z;
        g_csr_src[p3] = s.w;
    } else {
        for (int j = base; j < E; j++) {
            int pos = atomicAdd(&g_cursor[dst[j]], 1);
            g_csr_src[pos] = src[j];
        }
    }
}

// ---------------------------------------------------------------------------
// Fused softmax + aggregate: warp per dst node; 8 edges per chunk,
// software-pipelined: next chunk's (s, w) computed while current gathers fly.
// ---------------------------------------------------------------------------
__global__ void node_aggr_kernel(const float* __restrict__ bias,
                                 float* __restrict__ out, int N) {
    int warp = (blockIdx.x * blockDim.x + threadIdx.x) >> 5;
    int lane = threadIdx.x & 31;
    if (warp >= N) return;

    const int o0 = g_off[warp];
    const int o1 = o0 + g_deg[warp];
    const int lh = lane & 3;
    const int le = lane >> 2;
    const int gh = lane >> 3;
    const int gi = lane & 7;

    const float er_h = g_er[warp * HH + lh];
    const uint2* __restrict__ hh2 = reinterpret_cast<const uint2*>(g_hh);

    float ax = 0.f, ay = 0.f, az = 0.f, aw = 0.f;
    float s_acc = 0.f;

    const int deg = o1 - o0;
    const int nfull = deg >> 3;

    int s = 0; float w = 0.f;
    if (nfull > 0) {
        s = g_csr_src[o0 + le];
        w = __expf(lrelu(g_el[s * HH + lh] + er_h));
    }
    for (int f = 0; f < nfull; f++) {
        // prefetch next chunk while current gathers execute
        int s2 = 0; float w2 = 0.f;
        if (f + 1 < nfull) {
            s2 = g_csr_src[o0 + (f + 1) * 8 + le];
            w2 = __expf(lrelu(g_el[s2 * HH + lh] + er_h));
        }
        s_acc += w;
#pragma unroll
        for (int q = 0; q < 8; q++) {
            int   sq = __shfl_sync(0xffffffffu, s, q * 4);
            float wq = __shfl_sync(0xffffffffu, w, q * 4 + gh);
            uint2 v = hh2[(size_t)sq * 32 + gh * 8 + gi];
            float2 a = __half22float2(*reinterpret_cast<__half2*>(&v.x));
            float2 b = __half22float2(*reinterpret_cast<__half2*>(&v.y));
            ax += wq * a.x;
            ay += wq * a.y;
            az += wq * b.x;
            aw += wq * b.y;
        }
        s = s2; w = w2;
    }
    // tail (deg & 7 edges)
    int j0 = o0 + nfull * 8;
    if (j0 < o1) {
        int e = j0 + le;
        bool ok = (e < o1);
        int st = ok ? g_csr_src[e] : 0;
        float wt = 0.f;
        if (ok) wt = __expf(lrelu(g_el[st * HH + lh] + er_h));
        s_acc += wt;
        int rem = o1 - j0;   // 1..7, warp-uniform
        for (int q = 0; q < rem; q++) {
            int   sq = __shfl_sync(0xffffffffu, st, q * 4);
            float wq = __shfl_sync(0xffffffffu, wt, q * 4 + gh);
            uint2 v = hh2[(size_t)sq * 32 + gh * 8 + gi];
            float2 a = __half22float2(*reinterpret_cast<__half2*>(&v.x));
            float2 b = __half22float2(*reinterpret_cast<__half2*>(&v.y));
            ax += wq * a.x;
            ay += wq * a.y;
            az += wq * b.x;
            aw += wq * b.y;
        }
    }

    s_acc += __shfl_xor_sync(0xffffffffu, s_acc, 4);
    s_acc += __shfl_xor_sync(0xffffffffu, s_acc, 8);
    s_acc += __shfl_xor_sync(0xffffffffu, s_acc, 16);
    float sgh = __shfl_sync(0xffffffffu, s_acc, gh);
    float scale = (sgh > 0.f) ? (0.25f / sgh) : 0.f;
    ax *= scale; ay *= scale; az *= scale; aw *= scale;

    ax += __shfl_xor_sync(0xffffffffu, ax, 8);
    ay += __shfl_xor_sync(0xffffffffu, ay, 8);
    az += __shfl_xor_sync(0xffffffffu, az, 8);
    aw += __shfl_xor_sync(0xffffffffu, aw, 8);
    ax += __shfl_xor_sync(0xffffffffu, ax, 16);
    ay += __shfl_xor_sync(0xffffffffu, ay, 16);
    az += __shfl_xor_sync(0xffffffffu, az, 16);
    aw += __shfl_xor_sync(0xffffffffu, aw, 16);

    if (lane < 8) {
        int d = 4 * gi;
        float4 o;
        o.x = ax + 0.25f * (__ldg(&bias[d + 0]) + __ldg(&bias[DD + d + 0]) +
                            __ldg(&bias[2 * DD + d + 0]) + __ldg(&bias[3 * DD + d + 0]));
        o.y = ay + 0.25f * (__ldg(&bias[d + 1]) + __ldg(&bias[DD + d + 1]) +
                            __ldg(&bias[2 * DD + d + 1]) + __ldg(&bias[3 * DD + d + 1]));
        o.z = az + 0.25f * (__ldg(&bias[d + 2]) + __ldg(&bias[DD + d + 2]) +
                            __ldg(&bias[2 * DD + d + 2]) + __ldg(&bias[3 * DD + d + 2]));
        o.w = aw + 0.25f * (__ldg(&bias[d + 3]) + __ldg(&bias[DD + d + 3]) +
                            __ldg(&bias[2 * DD + d + 3]) + __ldg(&bias[3 * DD + d + 3]));
        *reinterpret_cast<float4*>(&out[warp * DD + d]) = o;
    }
}

// ---------------------------------------------------------------------------
extern "C" void kernel_launch(void* const* d_in, const int* in_sizes, int n_in,
                              void* d_out, int out_size) {
    const float* feat   = (const float*)d_in[0];
    const float* W      = (const float*)d_in[1];
    const float* attn_l = (const float*)d_in[2];
    const float* attn_r = (const float*)d_in[3];
    const float* bias   = (const float*)d_in[4];
    const int*   src    = (const int*)d_in[5];
    const int*   dst    = (const int*)d_in[6];
    float* out = (float*)d_out;

    const int N = in_sizes[0] / INF_;
    const int E = in_sizes[5];
    const int NB = (N + 1023) / 1024;
    const int E4 = (E + 3) / 4;

    cudaEventRecord(g_aux.evF, 0);
    cudaStreamWaitEvent(g_aux.s2, g_aux.evF, 0);

    gemm_elr_kernel<<<(N + 127) / 128, 256>>>(feat, W, attn_l, attn_r, N);

    init_kernel<<<(N + 255) / 256, 256, 0, g_aux.s2>>>(N);
    hist_kernel<<<(E4 + 255) / 256, 256, 0, g_aux.s2>>>(dst, E);
    scan_fused_kernel<<<NB, 1024, 0, g_aux.s2>>>(N);
    scatter_kernel<<<(E4 + 255) / 256, 256, 0, g_aux.s2>>>(src, dst, E);
    cudaEventRecord(g_aux.evJ, g_aux.s2);

    cudaStreamWaitEvent(0, g_aux.evJ, 0);
    {
        long long threads = (long long)N * 32;
        int blocks = (int)((threads + 255) / 256);
        node_aggr_kernel<<<blocks, 256>>>(bias, out, N);
    }
}

// round 10
// speedup vs baseline: 1.1786x; 1.1786x over previous
#include <cuda_runtime.h>
#include <cuda_fp16.h>
#include <math.h>

#define NMAX 100000
#define EMAX 1600000
#define HH 4
#define DD 32
#define HDIM 128
#define INF_ 128
#define NEG_SLOPE 0.2f

typedef unsigned long long ull;
typedef unsigned int uint_;

// Scratch (device globals — no allocation)
__device__ __align__(16) __half g_hh[NMAX * HDIM];   // [n][h][d] fp16
__device__ __align__(16) float g_el[NMAX * HH];
__device__ __align__(16) float g_er[NMAX * HH];
__device__ int g_deg[NMAX];
__device__ int g_off[NMAX];
__device__ int g_cursor[NMAX];
__device__ int g_bsum[128];
__device__ int g_csr_src[EMAX];

// Side stream + events (static-init, before harness mem checkpoints)
struct AuxStreams {
    cudaStream_t s2;
    cudaEvent_t evF, evJ;
    AuxStreams() {
        cudaStreamCreateWithFlags(&s2, cudaStreamNonBlocking);
        cudaEventCreateWithFlags(&evF, cudaEventDisableTiming);
        cudaEventCreateWithFlags(&evJ, cudaEventDisableTiming);
    }
};
static AuxStreams g_aux;

__device__ __forceinline__ float lrelu(float x) {
    return x > 0.f ? x : NEG_SLOPE * x;
}
__device__ __forceinline__ ull pk2(float lo, float hi) {
    ull r;
    asm("mov.b64 %0, {%1, %2};" : "=l"(r) : "f"(lo), "f"(hi));
    return r;
}
__device__ __forceinline__ void upk2(ull v, float& lo, float& hi) {
    asm("mov.b64 {%0, %1}, %2;" : "=f"(lo), "=f"(hi) : "l"(v));
}
__device__ __forceinline__ void ffma2(ull& d, ull a, ull b) {
    asm("fma.rn.f32x2 %0, %1, %2, %0;" : "+l"(d) : "l"(a), "l"(b));
}
__device__ __forceinline__ void cpa16(uint_ s, const void* g) {
    asm volatile("cp.async.cg.shared.global [%0], [%1], 16;" :: "r"(s), "l"(g));
}
__device__ __forceinline__ void cpa_commit() {
    asm volatile("cp.async.commit_group;");
}
__device__ __forceinline__ void cpa_wait_all() {
    asm volatile("cp.async.wait_group 0;");
}

// ---------------------------------------------------------------------------
__global__ void init_kernel(int N) {
    int i = blockIdx.x * blockDim.x + threadIdx.x;
    if (i < N) g_deg[i] = 0;
    if (i < 128) g_bsum[i] = -1;
}

// ---------------------------------------------------------------------------
// GEMM + fused el/er, double-buffered cp.async.  (frozen since R7)
// ---------------------------------------------------------------------------
__global__ void __launch_bounds__(256, 2)
gemm_elr_kernel(const float* __restrict__ feat,
                const float* __restrict__ W,
                const float* __restrict__ attn_l,
                const float* __restrict__ attn_r, int N) {
    __shared__ float sW[2][32][128];
    __shared__ float sFT[2][32][132];

    const int tid = threadIdx.x;
    const int row0 = blockIdx.x * 128;
    const int ry = tid >> 4;
    const int cx = tid & 15;
    const int r0 = ry * 8;
    const int c0a = 4 * cx;
    const int c0b = 64 + 4 * cx;
    const int hA = (cx < 8) ? 0 : 1;
    const int d0 = c0a & 31;

    int wk[4], wc4[4];
#pragma unroll
    for (int i = 0; i < 4; i++) {
        int idx = tid + i * 256;
        wk[i] = idx >> 5;
        wc4[i] = idx & 31;
    }
    int fr[4], fq[4];
#pragma unroll
    for (int i = 0; i < 4; i++) {
        int idx = tid + i * 256;
        fr[i] = idx >> 3;
        fq[i] = idx & 7;
    }

    ull acc2[32];
#pragma unroll
    for (int i = 0; i < 32; i++) acc2[i] = 0ull;

#pragma unroll
    for (int i = 0; i < 4; i++)
        cpa16((uint_)__cvta_generic_to_shared(&sW[0][wk[i]][wc4[i] * 4]),
              &W[wk[i] * HDIM + wc4[i] * 4]);
    cpa_commit();
    float4 fstage[4];
#pragma unroll
    for (int i = 0; i < 4; i++) {
        fstage[i] = make_float4(0.f, 0.f, 0.f, 0.f);
        if (row0 + fr[i] < N)
            fstage[i] = *reinterpret_cast<const float4*>(
                &feat[(size_t)(row0 + fr[i]) * INF_ + 4 * fq[i]]);
    }

    for (int kc = 0; kc < 4; kc++) {
        const int cur = kc & 1;
#pragma unroll
        for (int i = 0; i < 4; i++) {
            sFT[cur][4 * fq[i] + 0][fr[i]] = fstage[i].x;
            sFT[cur][4 * fq[i] + 1][fr[i]] = fstage[i].y;
            sFT[cur][4 * fq[i] + 2][fr[i]] = fstage[i].z;
            sFT[cur][4 * fq[i] + 3][fr[i]] = fstage[i].w;
        }
        cpa_wait_all();
        __syncthreads();

        if (kc < 3) {
            const int nxt = cur ^ 1;
            const int k0n = (kc + 1) * 32;
#pragma unroll
            for (int i = 0; i < 4; i++)
                cpa16((uint_)__cvta_generic_to_shared(&sW[nxt][wk[i]][wc4[i] * 4]),
                      &W[(k0n + wk[i]) * HDIM + wc4[i] * 4]);
            cpa_commit();
#pragma unroll
            for (int i = 0; i < 4; i++) {
                fstage[i] = make_float4(0.f, 0.f, 0.f, 0.f);
                if (row0 + fr[i] < N)
                    fstage[i] = *reinterpret_cast<const float4*>(
                        &feat[(size_t)(row0 + fr[i]) * INF_ + k0n + 4 * fq[i]]);
            }
        }

#pragma unroll 8
        for (int k = 0; k < 32; k++) {
            ulonglong2 f01 = *reinterpret_cast<const ulonglong2*>(&sFT[cur][k][r0]);
            ulonglong2 f23 = *reinterpret_cast<const ulonglong2*>(&sFT[cur][k][r0 + 4]);
            float4 wa = *reinterpret_cast<const float4*>(&sW[cur][k][c0a]);
            float4 wb = *reinterpret_cast<const float4*>(&sW[cur][k][c0b]);
            ull fp[4] = { f01.x, f01.y, f23.x, f23.y };
            ull wd[8] = { pk2(wa.x, wa.x), pk2(wa.y, wa.y),
                          pk2(wa.z, wa.z), pk2(wa.w, wa.w),
                          pk2(wb.x, wb.x), pk2(wb.y, wb.y),
                          pk2(wb.z, wb.z), pk2(wb.w, wb.w) };
#pragma unroll
            for (int rp = 0; rp < 4; rp++)
#pragma unroll
                for (int c = 0; c < 8; c++)
                    ffma2(acc2[rp * 8 + c], fp[rp], wd[c]);
        }
        __syncthreads();
    }

    float al[8], ar[8];
#pragma unroll
    for (int c = 0; c < 4; c++) {
        al[c]     = __ldg(&attn_l[c0a + c]);
        al[4 + c] = __ldg(&attn_l[c0b + c]);
        ar[c]     = __ldg(&attn_r[c0a + c]);
        ar[4 + c] = __ldg(&attn_r[c0b + c]);
    }

#pragma unroll
    for (int i = 0; i < 8; i++) {
        int rp = i >> 1, hi = i & 1;
        float hv[8];
#pragma unroll
        for (int c = 0; c < 8; c++) {
            float lo, hh;
            upk2(acc2[rp * 8 + c], lo, hh);
            hv[c] = hi ? hh : lo;
        }
        int row = row0 + r0 + i;
        bool valid = row < N;
        if (valid) {
            __half2 p0 = __floats2half2_rn(hv[0], hv[1]);
            __half2 p1 = __floats2half2_rn(hv[2], hv[3]);
            __half2 p2 = __floats2half2_rn(hv[4], hv[5]);
            __half2 p3 = __floats2half2_rn(hv[6], hv[7]);
            uint2 va = make_uint2(*(unsigned*)&p0, *(unsigned*)&p1);
            uint2 vb = make_uint2(*(unsigned*)&p2, *(unsigned*)&p3);
            *reinterpret_cast<uint2*>(&g_hh[((size_t)row * HH + hA) * DD + d0]) = va;
            *reinterpret_cast<uint2*>(&g_hh[((size_t)row * HH + hA + 2) * DD + d0]) = vb;
        }
        float plA = hv[0] * al[0] + hv[1] * al[1] + hv[2] * al[2] + hv[3] * al[3];
        float plB = hv[4] * al[4] + hv[5] * al[5] + hv[6] * al[6] + hv[7] * al[7];
        float prA = hv[0] * ar[0] + hv[1] * ar[1] + hv[2] * ar[2] + hv[3] * ar[3];
        float prB = hv[4] * ar[4] + hv[5] * ar[5] + hv[6] * ar[6] + hv[7] * ar[7];
#pragma unroll
        for (int o = 1; o <= 4; o <<= 1) {
            plA += __shfl_xor_sync(0xffffffffu, plA, o);
            plB += __shfl_xor_sync(0xffffffffu, plB, o);
            prA += __shfl_xor_sync(0xffffffffu, prA, o);
            prB += __shfl_xor_sync(0xffffffffu, prB, o);
        }
        if (valid) {
            if (cx == 0) {
                g_el[row * HH + 0] = plA; g_el[row * HH + 2] = plB;
                g_er[row * HH + 0] = prA; g_er[row * HH + 2] = prB;
            } else if (cx == 8) {
                g_el[row * HH + 1] = plA; g_el[row * HH + 3] = plB;
                g_er[row * HH + 1] = prA; g_er[row * HH + 3] = prB;
            }
        }
    }
}

// ---------------------------------------------------------------------------
// CSR build (int4-vectorized index reads — the KEPT half of the bisect)
// ---------------------------------------------------------------------------
__global__ void hist_kernel(const int* __restrict__ dst, int E) {
    int i = blockIdx.x * blockDim.x + threadIdx.x;
    int base = i * 4;
    if (base + 3 < E) {
        int4 d = *reinterpret_cast<const int4*>(&dst[base]);
        atomicAdd(&g_deg[d.x], 1);
        atomicAdd(&g_deg[d.y], 1);
        atomicAdd(&g_deg[d.z], 1);
        atomicAdd(&g_deg[d.w], 1);
    } else {
        for (int j = base; j < E; j++) atomicAdd(&g_deg[dst[j]], 1);
    }
}

// Single-kernel scan with decoupled lookback (<=128 co-resident blocks).
__global__ void scan_fused_kernel(int N) {
    __shared__ int sm[1024];
    __shared__ int spre[128];
    int tid = threadIdx.x;
    int b = blockIdx.x;
    int gid = b * 1024 + tid;
    int v = (gid < N) ? g_deg[gid] : 0;
    sm[tid] = v;
    __syncthreads();
#pragma unroll
    for (int o = 1; o < 1024; o <<= 1) {
        int t = (tid >= o) ? sm[tid - o] : 0;
        __syncthreads();
        sm[tid] += t;
        __syncthreads();
    }
    if (tid == 0) atomicExch(&g_bsum[b], sm[1023]);
    int pv = 0;
    if (tid < b) {
        volatile int* p = &g_bsum[tid];
        int x;
        do { x = *p; } while (x < 0);
        pv = x;
    }
    if (tid < 128) spre[tid] = pv;
    __syncthreads();
#pragma unroll
    for (int o = 64; o > 0; o >>= 1) {
        if (tid < o) spre[tid] += spre[tid + o];
        __syncthreads();
    }
    int prefix = spre[0];
    if (gid < N) {
        int o = sm[tid] - v + prefix;
        g_off[gid] = o;
        g_cursor[gid] = o;
    }
}

__global__ void scatter_kernel(const int* __restrict__ src,
                               const int* __restrict__ dst, int E) {
    int i = blockIdx.x * blockDim.x + threadIdx.x;
    int base = i * 4;
    if (base + 3 < E) {
        int4 d = *reinterpret_cast<const int4*>(&dst[base]);
        int4 s = *reinterpret_cast<const int4*>(&src[base]);
        int p0 = atomicAdd(&g_cursor[d.x], 1);
        int p1 = atomicAdd(&g_cursor[d.y], 1);
        int p2 = atomicAdd(&g_cursor[d.z], 1);
        int p3 = atomicAdd(&g_cursor[d.w], 1);
        g_csr_src[p0] = s.x;
        g_csr_src[p1] = s.y;
        g_csr_src[p2] = s.z;
        g_csr_src[p3] = s.w;
    } else {
        for (int j = base; j < E; j++) {
            int pos = atomicAdd(&g_cursor[dst[j]], 1);
            g_csr_src[pos] = src[j];
        }
    }
}

// ---------------------------------------------------------------------------
// Fused softmax + aggregate: warp per dst node; 8 edges per chunk.
// EXACT R8 form (pipeline reverted — the other half of the bisect).
// ---------------------------------------------------------------------------
__global__ void node_aggr_kernel(const float* __restrict__ bias,
                                 float* __restrict__ out, int N) {
    int warp = (blockIdx.x * blockDim.x + threadIdx.x) >> 5;
    int lane = threadIdx.x & 31;
    if (warp >= N) return;

    const int o0 = g_off[warp];
    const int o1 = o0 + g_deg[warp];
    const int lh = lane & 3;
    const int le = lane >> 2;
    const int gh = lane >> 3;
    const int gi = lane & 7;

    const float er_h = g_er[warp * HH + lh];
    const uint2* __restrict__ hh2 = reinterpret_cast<const uint2*>(g_hh);

    float ax = 0.f, ay = 0.f, az = 0.f, aw = 0.f;
    float s_acc = 0.f;

    int j0 = o0;
    for (; j0 + 8 <= o1; j0 += 8) {
        int s = g_csr_src[j0 + le];
        float w = __expf(lrelu(g_el[s * HH + lh] + er_h));
        s_acc += w;
#pragma unroll
        for (int q = 0; q < 8; q++) {
            int   sq = __shfl_sync(0xffffffffu, s, q * 4);
            float wq = __shfl_sync(0xffffffffu, w, q * 4 + gh);
            uint2 v = hh2[(size_t)sq * 32 + gh * 8 + gi];
            float2 a = __half22float2(*reinterpret_cast<__half2*>(&v.x));
            float2 b = __half22float2(*reinterpret_cast<__half2*>(&v.y));
            ax += wq * a.x;
            ay += wq * a.y;
            az += wq * b.x;
            aw += wq * b.y;
        }
    }
    if (j0 < o1) {
        int e = j0 + le;
        bool ok = (e < o1);
        int s = ok ? g_csr_src[e] : 0;
        float w = 0.f;
        if (ok) w = __expf(lrelu(g_el[s * HH + lh] + er_h));
        s_acc += w;
        int rem = o1 - j0;   // warp-uniform, 1..7
        for (int q = 0; q < rem; q++) {
            int   sq = __shfl_sync(0xffffffffu, s, q * 4);
            float wq = __shfl_sync(0xffffffffu, w, q * 4 + gh);
            uint2 v = hh2[(size_t)sq * 32 + gh * 8 + gi];
            float2 a = __half22float2(*reinterpret_cast<__half2*>(&v.x));
            float2 b = __half22float2(*reinterpret_cast<__half2*>(&v.y));
            ax += wq * a.x;
            ay += wq * a.y;
            az += wq * b.x;
            aw += wq * b.y;
        }
    }

    s_acc += __shfl_xor_sync(0xffffffffu, s_acc, 4);
    s_acc += __shfl_xor_sync(0xffffffffu, s_acc, 8);
    s_acc += __shfl_xor_sync(0xffffffffu, s_acc, 16);
    float sgh = __shfl_sync(0xffffffffu, s_acc, gh);
    float scale = (sgh > 0.f) ? (0.25f / sgh) : 0.f;
    ax *= scale; ay *= scale; az *= scale; aw *= scale;

    ax += __shfl_xor_sync(0xffffffffu, ax, 8);
    ay += __shfl_xor_sync(0xffffffffu, ay, 8);
    az += __shfl_xor_sync(0xffffffffu, az, 8);
    aw += __shfl_xor_sync(0xffffffffu, aw, 8);
    ax += __shfl_xor_sync(0xffffffffu, ax, 16);
    ay += __shfl_xor_sync(0xffffffffu, ay, 16);
    az += __shfl_xor_sync(0xffffffffu, az, 16);
    aw += __shfl_xor_sync(0xffffffffu, aw, 16);

    if (lane < 8) {
        int d = 4 * gi;
        float4 o;
        o.x = ax + 0.25f * (__ldg(&bias[d + 0]) + __ldg(&bias[DD + d + 0]) +
                            __ldg(&bias[2 * DD + d + 0]) + __ldg(&bias[3 * DD + d + 0]));
        o.y = ay + 0.25f * (__ldg(&bias[d + 1]) + __ldg(&bias[DD + d + 1]) +
                            __ldg(&bias[2 * DD + d + 1]) + __ldg(&bias[3 * DD + d + 1]));
        o.z = az + 0.25f * (__ldg(&bias[d + 2]) + __ldg(&bias[DD + d + 2]) +
                            __ldg(&bias[2 * DD + d + 2]) + __ldg(&bias[3 * DD + d + 2]));
        o.w = aw + 0.25f * (__ldg(&bias[d + 3]) + __ldg(&bias[DD + d + 3]) +
                            __ldg(&bias[2 * DD + d + 3]) + __ldg(&bias[3 * DD + d + 3]));
        *reinterpret_cast<float4*>(&out[warp * DD + d]) = o;
    }
}

// ---------------------------------------------------------------------------
extern "C" void kernel_launch(void* const* d_in, const int* in_sizes, int n_in,
                              void* d_out, int out_size) {
    const float* feat   = (const float*)d_in[0];
    const float* W      = (const float*)d_in[1];
    const float* attn_l = (const float*)d_in[2];
    const float* attn_r = (const float*)d_in[3];
    const float* bias   = (const float*)d_in[4];
    const int*   src    = (const int*)d_in[5];
    const int*   dst    = (const int*)d_in[6];
    float* out = (float*)d_out;

    const int N = in_sizes[0] / INF_;
    const int E = in_sizes[5];
    const int NB = (N + 1023) / 1024;
    const int E4 = (E + 3) / 4;

    cudaEventRecord(g_aux.evF, 0);
    cudaStreamWaitEvent(g_aux.s2, g_aux.evF, 0);

    gemm_elr_kernel<<<(N + 127) / 128, 256>>>(feat, W, attn_l, attn_r, N);

    init_kernel<<<(N + 255) / 256, 256, 0, g_aux.s2>>>(N);
    hist_kernel<<<(E4 + 255) / 256, 256, 0, g_aux.s2>>>(dst, E);
    scan_fused_kernel<<<NB, 1024, 0, g_aux.s2>>>(N);
    scatter_kernel<<<(E4 + 255) / 256, 256, 0, g_aux.s2>>>(src, dst, E);
    cudaEventRecord(g_aux.evJ, g_aux.s2);

    cudaStreamWaitEvent(0, g_aux.evJ, 0);
    {
        long long threads = (long long)N * 32;
        int blocks = (int)((threads + 255) / 256);
        node_aggr_kernel<<<blocks, 256>>>(bias, out, N);
    }
}